// round 9
// baseline (speedup 1.0000x reference)
#include <cuda_runtime.h>
#include <cuda_bf16.h>
#include <stdint.h>
#include <math.h>

#define NE 8
#define HID 2048
#define INTER 1408
#define TOT 8192
#define MAXTILES 96
#define MAXGRIDY 72

// ---------------------------------------------------------------------------
// Device globals
// ---------------------------------------------------------------------------
__device__ int g_tile_expert[MAXTILES];
__device__ int g_tile_row0[MAXTILES];
__device__ int g_tile_nrows[MAXTILES];
__device__ int g_ntiles;

__device__ __nv_bfloat16 g_xh[(size_t)TOT * HID];
__device__ __nv_bfloat16 g_xl[(size_t)TOT * HID];
// transposed weights: [E][N][K], K contiguous
__device__ __nv_bfloat16 g_wgh[(size_t)NE * INTER * HID];
__device__ __nv_bfloat16 g_wgl[(size_t)NE * INTER * HID];
__device__ __nv_bfloat16 g_wuh[(size_t)NE * INTER * HID];
__device__ __nv_bfloat16 g_wul[(size_t)NE * INTER * HID];
__device__ __nv_bfloat16 g_wdh[(size_t)NE * HID * INTER];
__device__ __nv_bfloat16 g_wdl[(size_t)NE * HID * INTER];
__device__ __nv_bfloat16 g_hh[(size_t)TOT * INTER];
__device__ __nv_bfloat16 g_hl[(size_t)TOT * INTER];

// ---------------------------------------------------------------------------
// Helpers (base-target PTX: mma.sync sm_80, cp.async sm_80, ldmatrix sm_75)
// ---------------------------------------------------------------------------
__device__ __forceinline__ uint32_t smem_u32(const void* p) {
    uint32_t a;
    asm("{ .reg .u64 t; cvta.to.shared.u64 t, %1; cvt.u32.u64 %0, t; }"
        : "=r"(a) : "l"(p));
    return a;
}

__device__ __forceinline__ void cp16(uint32_t dst, const void* src, int srcsize) {
    asm volatile("cp.async.cg.shared.global [%0], [%1], 16, %2;"
                 :: "r"(dst), "l"(src), "r"(srcsize));
}
#define CP_COMMIT() asm volatile("cp.async.commit_group;")
#define CP_WAIT0()  asm volatile("cp.async.wait_group 0;")

__device__ __forceinline__ void mma16816(float& c0, float& c1, float& c2, float& c3,
                                         const uint32_t a[4], const uint32_t* b) {
    asm volatile(
        "mma.sync.aligned.m16n8k16.row.col.f32.bf16.bf16.f32 "
        "{%0,%1,%2,%3},{%4,%5,%6,%7},{%8,%9},{%0,%1,%2,%3};"
        : "+f"(c0), "+f"(c1), "+f"(c2), "+f"(c3)
        : "r"(a[0]), "r"(a[1]), "r"(a[2]), "r"(a[3]), "r"(b[0]), "r"(b[1]));
}
#define MMA(C, A, B) mma16816((C)[0], (C)[1], (C)[2], (C)[3], A, B)

__device__ __forceinline__ void ldm_x4(uint32_t r[4], uint32_t addr) {
    asm volatile("ldmatrix.sync.aligned.m8n8.x4.shared.b16 {%0,%1,%2,%3}, [%4];"
                 : "=r"(r[0]), "=r"(r[1]), "=r"(r[2]), "=r"(r[3]) : "r"(addr));
}

// Row stride 80 B (conflict-free for cp.async stores and ldmatrix reads)
#define RSTR 80

// A fragment group (16 rows x 16 k): one ldmatrix.x4 -> mma operand order
__device__ __forceinline__ void fragA(uint32_t a[4], uint32_t tile, int rb, int k0, int lane) {
    uint32_t addr = tile + (uint32_t)(rb + (lane & 15)) * RSTR
                         + (uint32_t)(k0 + (lane >> 4) * 8) * 2;
    ldm_x4(a, addr);
}
// B fragment pair (two adjacent n-octets x 16 k from [n][k] tile)
__device__ __forceinline__ void fragB2(uint32_t b[4], uint32_t tile, int nb, int k0, int lane) {
    uint32_t addr = tile + (uint32_t)(nb + ((lane >> 4) * 8) + (lane & 7)) * RSTR
                         + (uint32_t)(k0 + ((lane >> 3) & 1) * 8) * 2;
    ldm_x4(b, addr);
}

// 128-row x 32-col bf16 tile via cp.async; per-thread sizes precomputed
__device__ __forceinline__ void load_tile128(uint32_t sdst, const __nv_bfloat16* src,
                                             int ldk, int k0, int s0, int s1, int tid) {
    const int r = tid >> 2, c = tid & 3;
    cp16(sdst + r * RSTR + c * 16, src + (size_t)r * ldk + k0 + c * 8, s0);
    cp16(sdst + (r + 64) * RSTR + c * 16, src + (size_t)(r + 64) * ldk + k0 + c * 8, s1);
}
__device__ __forceinline__ void load_tile64(uint32_t sdst, const __nv_bfloat16* src,
                                            int ldk, int k0, int tid) {
    const int r = tid >> 2, c = tid & 3;
    cp16(sdst + r * RSTR + c * 16, src + (size_t)r * ldk + k0 + c * 8, 16);
}

// ---------------------------------------------------------------------------
// Prep kernels
// ---------------------------------------------------------------------------
__global__ void convert_x(const float* __restrict__ x, const int* __restrict__ tpe) {
    if (blockIdx.x == 0 && threadIdx.x == 0) {
        int off = 0, nt = 0;
        for (int e = 0; e < NE; e++) {
            int n = tpe[e];
            for (int r = 0; r < n; r += 128) {
                g_tile_expert[nt] = e;
                g_tile_row0[nt]   = off + r;
                g_tile_nrows[nt]  = (n - r < 128) ? (n - r) : 128;
                nt++;
            }
            off += n;
        }
        g_ntiles = nt;
    }
    const size_t n4 = (size_t)TOT * HID / 4;
    for (size_t i = blockIdx.x * blockDim.x + threadIdx.x; i < n4;
         i += (size_t)gridDim.x * blockDim.x) {
        float4 v = ((const float4*)x)[i];
        __nv_bfloat16 h0 = __float2bfloat16(v.x), h1 = __float2bfloat16(v.y);
        __nv_bfloat16 h2 = __float2bfloat16(v.z), h3 = __float2bfloat16(v.w);
        __nv_bfloat16 l0 = __float2bfloat16(v.x - __bfloat162float(h0));
        __nv_bfloat16 l1 = __float2bfloat16(v.y - __bfloat162float(h1));
        __nv_bfloat16 l2 = __float2bfloat16(v.z - __bfloat162float(h2));
        __nv_bfloat16 l3 = __float2bfloat16(v.w - __bfloat162float(h3));
        uint32_t ph0 = (uint32_t)__bfloat16_as_ushort(h0) | ((uint32_t)__bfloat16_as_ushort(h1) << 16);
        uint32_t ph1 = (uint32_t)__bfloat16_as_ushort(h2) | ((uint32_t)__bfloat16_as_ushort(h3) << 16);
        uint32_t pl0 = (uint32_t)__bfloat16_as_ushort(l0) | ((uint32_t)__bfloat16_as_ushort(l1) << 16);
        uint32_t pl1 = (uint32_t)__bfloat16_as_ushort(l2) | ((uint32_t)__bfloat16_as_ushort(l3) << 16);
        ((uint2*)g_xh)[i] = make_uint2(ph0, ph1);
        ((uint2*)g_xl)[i] = make_uint2(pl0, pl1);
    }
}

__device__ __forceinline__ uint32_t pack_hi(float v0, float v1, uint32_t& lo) {
    __nv_bfloat16 h0 = __float2bfloat16(v0), h1 = __float2bfloat16(v1);
    __nv_bfloat16 l0 = __float2bfloat16(v0 - __bfloat162float(h0));
    __nv_bfloat16 l1 = __float2bfloat16(v1 - __bfloat162float(h1));
    lo = (uint32_t)__bfloat16_as_ushort(l0) | ((uint32_t)__bfloat16_as_ushort(l1) << 16);
    return (uint32_t)__bfloat16_as_ushort(h0) | ((uint32_t)__bfloat16_as_ushort(h1) << 16);
}

// z<NE: wg, z>=NE: wu.  [E][HID][INTER] fp32 -> [E][INTER][HID] bf16 hi/lo.
__global__ void transpose_cvt_gu(const float* __restrict__ wg,
                                 const float* __restrict__ wu) {
    __shared__ float t[32][33];
    const int z = blockIdx.z;
    const int e = z & (NE - 1);
    const bool isu = z >= NE;
    const float* src = (isu ? wu : wg) + (size_t)e * HID * INTER;
    __nv_bfloat16* dh = (isu ? g_wuh : g_wgh) + (size_t)e * HID * INTER;
    __nv_bfloat16* dl = (isu ? g_wul : g_wgl) + (size_t)e * HID * INTER;
    const int k0 = blockIdx.x * 32, n0 = blockIdx.y * 32;
    const int tx = threadIdx.x, ty = threadIdx.y;
#pragma unroll
    for (int jj = 0; jj < 2; jj++) {
        const int kl = ty + jj * 16;
        float2 v = *(const float2*)(src + (size_t)(k0 + kl) * INTER + n0 + 2 * tx);
        t[kl][2 * tx] = v.x;
        t[kl][2 * tx + 1] = v.y;
    }
    __syncthreads();
#pragma unroll
    for (int jj = 0; jj < 2; jj++) {
        const int nl = ty + jj * 16;
        uint32_t lo;
        uint32_t hi = pack_hi(t[2 * tx][nl], t[2 * tx + 1][nl], lo);
        const size_t o = (size_t)(n0 + nl) * HID + k0 + 2 * tx;
        *(uint32_t*)(dh + o) = hi;
        *(uint32_t*)(dl + o) = lo;
    }
}

// [E][INTER][HID] fp32 -> [E][HID][INTER] bf16 hi/lo
__global__ void transpose_cvt_d(const float* __restrict__ wd) {
    __shared__ float t[32][33];
    const int e = blockIdx.z;
    const float* src = wd + (size_t)e * INTER * HID;
    __nv_bfloat16* dh = g_wdh + (size_t)e * INTER * HID;
    __nv_bfloat16* dl = g_wdl + (size_t)e * INTER * HID;
    const int k0 = blockIdx.x * 32, n0 = blockIdx.y * 32;
    const int tx = threadIdx.x, ty = threadIdx.y;
#pragma unroll
    for (int jj = 0; jj < 2; jj++) {
        const int kl = ty + jj * 16;
        float2 v = *(const float2*)(src + (size_t)(k0 + kl) * HID + n0 + 2 * tx);
        t[kl][2 * tx] = v.x;
        t[kl][2 * tx + 1] = v.y;
    }
    __syncthreads();
#pragma unroll
    for (int jj = 0; jj < 2; jj++) {
        const int nl = ty + jj * 16;
        uint32_t lo;
        uint32_t hi = pack_hi(t[2 * tx][nl], t[2 * tx + 1][nl], lo);
        const size_t o = (size_t)(n0 + nl) * INTER + k0 + 2 * tx;
        *(uint32_t*)(dh + o) = hi;
        *(uint32_t*)(dl + o) = lo;
    }
}

// ---------------------------------------------------------------------------
// Fused gate+up grouped GEMM. CTA: M=128 x N=64 (per matrix), BK=32.
// 8 warps (4 M x 2 N), warp = 32x32 per matrix. 2-stage, 1 barrier/chunk.
// MMAs emitted TERM-MAJOR: 8 independent accumulators between dependent pairs.
// Stage layout (40960 B): Ah 0, Al 10240, Bgh 20480, Bgl 25600, Buh 30720, Bul 35840
// ---------------------------------------------------------------------------
#define GU_BUF 40960
#define GU_SMEM (2 * GU_BUF)

__global__ void __launch_bounds__(256, 2) k_gateup() {
    const int t = blockIdx.y;
    if (t >= g_ntiles) return;
    const int e     = __ldg(&g_tile_expert[t]);
    const int row0  = __ldg(&g_tile_row0[t]);
    const int nrows = __ldg(&g_tile_nrows[t]);
    const int n0    = blockIdx.x * 64;

    extern __shared__ char smem[];
    const uint32_t sb = smem_u32(smem);
    const int tid  = threadIdx.x;
    const int lane = tid & 31;
    const int wid  = tid >> 5;
    const int wm   = wid & 3;
    const int wn   = wid >> 2;
    const int s0 = ((tid >> 2) < nrows) ? 16 : 0;
    const int s1 = ((tid >> 2) + 64 < nrows) ? 16 : 0;

    const __nv_bfloat16* xh = g_xh + (size_t)row0 * HID;
    const __nv_bfloat16* xl = g_xl + (size_t)row0 * HID;
    const size_t wbase = (size_t)e * INTER * HID + (size_t)n0 * HID;
    const __nv_bfloat16* gh = g_wgh + wbase;
    const __nv_bfloat16* gl = g_wgl + wbase;
    const __nv_bfloat16* uh = g_wuh + wbase;
    const __nv_bfloat16* ul = g_wul + wbase;

    float cg[2][4][4], cu[2][4][4];
#pragma unroll
    for (int i = 0; i < 2; i++)
#pragma unroll
        for (int j = 0; j < 4; j++)
#pragma unroll
            for (int k = 0; k < 4; k++) { cg[i][j][k] = 0.f; cu[i][j][k] = 0.f; }

#define GU_LOAD(b, k0)                                              \
    do {                                                            \
        uint32_t o = sb + (b) * GU_BUF;                             \
        load_tile128(o,          xh, HID, (k0), s0, s1, tid);       \
        load_tile128(o + 10240,  xl, HID, (k0), s0, s1, tid);       \
        load_tile64(o + 20480,   gh, HID, (k0), tid);               \
        load_tile64(o + 25600,   gl, HID, (k0), tid);               \
        load_tile64(o + 30720,   uh, HID, (k0), tid);               \
        load_tile64(o + 35840,   ul, HID, (k0), tid);               \
        CP_COMMIT();                                                \
    } while (0)

    GU_LOAD(0, 0);
    const int KT = HID / 32;
    for (int kt = 0; kt < KT; kt++) {
        CP_WAIT0();
        __syncthreads();
        if (kt + 1 < KT) GU_LOAD((kt + 1) & 1, (kt + 1) * 32);
        const uint32_t buf = sb + (kt & 1) * GU_BUF;
#pragma unroll
        for (int ks = 0; ks < 2; ks++) {
            const int k0 = ks * 16;
            uint32_t Ah0[4], Ah1[4], Al0[4], Al1[4];
            fragA(Ah0, buf,         wm * 32,      k0, lane);
            fragA(Ah1, buf,         wm * 32 + 16, k0, lane);
            fragA(Al0, buf + 10240, wm * 32,      k0, lane);
            fragA(Al1, buf + 10240, wm * 32 + 16, k0, lane);
#pragma unroll
            for (int p = 0; p < 2; p++) {
                const int nb = wn * 32 + p * 16;
                uint32_t Bgh[4], Bgl[4], Buh[4], Bul[4];
                fragB2(Bgh, buf + 20480, nb, k0, lane);
                fragB2(Bgl, buf + 25600, nb, k0, lane);
                fragB2(Buh, buf + 30720, nb, k0, lane);
                fragB2(Bul, buf + 35840, nb, k0, lane);
                const int q = p * 2;
                // term 1: A-hi x B-hi -- 8 independent accumulators
                MMA(cg[0][q],   Ah0, Bgh);
                MMA(cg[1][q],   Ah1, Bgh);
                MMA(cg[0][q+1], Ah0, Bgh + 2);
                MMA(cg[1][q+1], Ah1, Bgh + 2);
                MMA(cu[0][q],   Ah0, Buh);
                MMA(cu[1][q],   Ah1, Buh);
                MMA(cu[0][q+1], Ah0, Buh + 2);
                MMA(cu[1][q+1], Ah1, Buh + 2);
                // term 2: A-hi x B-lo
                MMA(cg[0][q],   Ah0, Bgl);
                MMA(cg[1][q],   Ah1, Bgl);
                MMA(cg[0][q+1], Ah0, Bgl + 2);
                MMA(cg[1][q+1], Ah1, Bgl + 2);
                MMA(cu[0][q],   Ah0, Bul);
                MMA(cu[1][q],   Ah1, Bul);
                MMA(cu[0][q+1], Ah0, Bul + 2);
                MMA(cu[1][q+1], Ah1, Bul + 2);
                // term 3: A-lo x B-hi
                MMA(cg[0][q],   Al0, Bgh);
                MMA(cg[1][q],   Al1, Bgh);
                MMA(cg[0][q+1], Al0, Bgh + 2);
                MMA(cg[1][q+1], Al1, Bgh + 2);
                MMA(cu[0][q],   Al0, Buh);
                MMA(cu[1][q],   Al1, Buh);
                MMA(cu[0][q+1], Al0, Buh + 2);
                MMA(cu[1][q+1], Al1, Buh + 2);
            }
        }
    }

    // epilogue: silu(gate)*up -> h hi/lo
#pragma unroll
    for (int mt = 0; mt < 2; mt++)
#pragma unroll
        for (int half = 0; half < 2; half++) {
            const int r = wm * 32 + mt * 16 + half * 8 + (lane >> 2);
            if (r < nrows) {
                __nv_bfloat16* hhp = g_hh + (size_t)(row0 + r) * INTER + n0 + wn * 32;
                __nv_bfloat16* hlp = g_hl + (size_t)(row0 + r) * INTER + n0 + wn * 32;
#pragma unroll
                for (int nt = 0; nt < 4; nt++) {
                    const float gg0 = cg[mt][nt][half * 2], gg1 = cg[mt][nt][half * 2 + 1];
                    const float uu0 = cu[mt][nt][half * 2], uu1 = cu[mt][nt][half * 2 + 1];
                    const float h0 = uu0 * gg0 / (1.f + __expf(-gg0));
                    const float h1 = uu1 * gg1 / (1.f + __expf(-gg1));
                    uint32_t lo;
                    uint32_t hi = pack_hi(h0, h1, lo);
                    const int col = nt * 8 + (lane & 3) * 2;
                    *(uint32_t*)(hhp + col) = hi;
                    *(uint32_t*)(hlp + col) = lo;
                }
            }
        }
}

// ---------------------------------------------------------------------------
// Down grouped GEMM. CTA: M=128 x N=128, BK=32, 8 warps (4 x 2), warp 32x64.
// Term-major MMA order (4 independent chains between dependent pairs).
// Stage layout (40960 B): Ah 0, Al 10240, Bh 20480, Bl 30720
// ---------------------------------------------------------------------------
#define DN_BUF 40960
#define DN_SMEM (2 * DN_BUF)

__global__ void __launch_bounds__(256, 2) k_down(const float* __restrict__ probs,
                                                 float* __restrict__ out) {
    const int t = blockIdx.y;
    if (t >= g_ntiles) return;
    const int e     = __ldg(&g_tile_expert[t]);
    const int row0  = __ldg(&g_tile_row0[t]);
    const int nrows = __ldg(&g_tile_nrows[t]);
    const int n0    = blockIdx.x * 128;

    extern __shared__ char smem[];
    const uint32_t sb = smem_u32(smem);
    const int tid  = threadIdx.x;
    const int lane = tid & 31;
    const int wid  = tid >> 5;
    const int wm   = wid & 3;
    const int wn   = wid >> 2;
    const int s0 = ((tid >> 2) < nrows) ? 16 : 0;
    const int s1 = ((tid >> 2) + 64 < nrows) ? 16 : 0;

    const __nv_bfloat16* ah = g_hh + (size_t)row0 * INTER;
    const __nv_bfloat16* al = g_hl + (size_t)row0 * INTER;
    const size_t wbase = (size_t)e * HID * INTER + (size_t)n0 * INTER;
    const __nv_bfloat16* bh  = g_wdh + wbase;
    const __nv_bfloat16* blo = g_wdl + wbase;

    float cc[2][8][4];
#pragma unroll
    for (int i = 0; i < 2; i++)
#pragma unroll
        for (int j = 0; j < 8; j++)
#pragma unroll
            for (int k = 0; k < 4; k++) cc[i][j][k] = 0.f;

#define DN_LOAD(b, k0)                                                  \
    do {                                                                \
        uint32_t o = sb + (b) * DN_BUF;                                 \
        load_tile128(o,          ah,  INTER, (k0), s0, s1, tid);        \
        load_tile128(o + 10240,  al,  INTER, (k0), s0, s1, tid);        \
        load_tile128(o + 20480,  bh,  INTER, (k0), 16, 16, tid);        \
        load_tile128(o + 30720,  blo, INTER, (k0), 16, 16, tid);        \
        CP_COMMIT();                                                    \
    } while (0)

    DN_LOAD(0, 0);
    const int KT = INTER / 32;
    for (int kt = 0; kt < KT; kt++) {
        CP_WAIT0();
        __syncthreads();
        if (kt + 1 < KT) DN_LOAD((kt + 1) & 1, (kt + 1) * 32);
        const uint32_t buf = sb + (kt & 1) * DN_BUF;
#pragma unroll
        for (int ks = 0; ks < 2; ks++) {
            const int k0 = ks * 16;
            uint32_t Ah0[4], Ah1[4], Al0[4], Al1[4];
            fragA(Ah0, buf,         wm * 32,      k0, lane);
            fragA(Ah1, buf,         wm * 32 + 16, k0, lane);
            fragA(Al0, buf + 10240, wm * 32,      k0, lane);
            fragA(Al1, buf + 10240, wm * 32 + 16, k0, lane);
#pragma unroll
            for (int p = 0; p < 4; p++) {
                const int nb = wn * 64 + p * 16;
                uint32_t Fbh[4], Fbl[4];
                fragB2(Fbh, buf + 20480, nb, k0, lane);
                fragB2(Fbl, buf + 30720, nb, k0, lane);
                const int q = p * 2;
                // term 1 (4 independent chains)
                MMA(cc[0][q],   Ah0, Fbh);
                MMA(cc[1][q],   Ah1, Fbh);
                MMA(cc[0][q+1], Ah0, Fbh + 2);
                MMA(cc[1][q+1], Ah1, Fbh + 2);
                // term 2
                MMA(cc[0][q],   Ah0, Fbl);
                MMA(cc[1][q],   Ah1, Fbl);
                MMA(cc[0][q+1], Ah0, Fbl + 2);
                MMA(cc[1][q+1], Ah1, Fbl + 2);
                // term 3
                MMA(cc[0][q],   Al0, Fbh);
                MMA(cc[1][q],   Al1, Fbh);
                MMA(cc[0][q+1], Al0, Fbh + 2);
                MMA(cc[1][q+1], Al1, Fbh + 2);
            }
        }
    }

    // epilogue: scale by probs, write fp32 out
#pragma unroll
    for (int mt = 0; mt < 2; mt++)
#pragma unroll
        for (int half = 0; half < 2; half++) {
            const int r = wm * 32 + mt * 16 + half * 8 + (lane >> 2);
            if (r < nrows) {
                const float p = probs[row0 + r];
                float* op = out + (size_t)(row0 + r) * HID + n0 + wn * 64;
#pragma unroll
                for (int nt = 0; nt < 8; nt++) {
                    const int col = nt * 8 + (lane & 3) * 2;
                    float2 v;
                    v.x = p * cc[mt][nt][half * 2];
                    v.y = p * cc[mt][nt][half * 2 + 1];
                    *(float2*)(op + col) = v;
                }
            }
        }
}

// ---------------------------------------------------------------------------
// Launch
// ---------------------------------------------------------------------------
extern "C" void kernel_launch(void* const* d_in, const int* in_sizes, int n_in,
                              void* d_out, int out_size) {
    const float* x     = (const float*)d_in[0];
    const float* probs = (const float*)d_in[1];
    const float* wg    = (const float*)d_in[2];
    const float* wu    = (const float*)d_in[3];
    const float* wd    = (const float*)d_in[4];
    const int*   tpe   = (const int*)d_in[5];
    float*       out   = (float*)d_out;

    cudaFuncSetAttribute(k_gateup, cudaFuncAttributeMaxDynamicSharedMemorySize, GU_SMEM);
    cudaFuncSetAttribute(k_down,   cudaFuncAttributeMaxDynamicSharedMemorySize, DN_SMEM);

    convert_x<<<2048, 256>>>(x, tpe);

    dim3 tb(16, 16);
    transpose_cvt_gu<<<dim3(HID / 32, INTER / 32, 2 * NE), tb>>>(wg, wu);
    transpose_cvt_d<<<dim3(INTER / 32, HID / 32, NE), tb>>>(wd);

    k_gateup<<<dim3(INTER / 64, MAXGRIDY), 256, GU_SMEM>>>();
    k_down<<<dim3(HID / 128, MAXGRIDY), 256, DN_SMEM>>>(probs, out);
}

// round 10
// speedup vs baseline: 2.3265x; 2.3265x over previous
#include <cuda_runtime.h>
#include <cuda_fp16.h>
#include <stdint.h>
#include <math.h>

#define NE 8
#define HID 2048
#define INTER 1408
#define TOT 8192
#define MAXTILES 96
#define MAXGRIDY 72

// ---------------------------------------------------------------------------
// Device globals (fp16 single plane everywhere)
// ---------------------------------------------------------------------------
__device__ int g_tile_expert[MAXTILES];
__device__ int g_tile_row0[MAXTILES];
__device__ int g_tile_nrows[MAXTILES];
__device__ int g_ntiles;

__device__ __half g_x[(size_t)TOT * HID];
// transposed weights: [E][N][K], K contiguous
__device__ __half g_wg[(size_t)NE * INTER * HID];
__device__ __half g_wu[(size_t)NE * INTER * HID];
__device__ __half g_wd[(size_t)NE * HID * INTER];
__device__ __half g_h[(size_t)TOT * INTER];

// ---------------------------------------------------------------------------
// Helpers (base-target PTX: mma.sync sm_80, cp.async sm_80, ldmatrix sm_75)
// ---------------------------------------------------------------------------
__device__ __forceinline__ uint32_t smem_u32(const void* p) {
    uint32_t a;
    asm("{ .reg .u64 t; cvta.to.shared.u64 t, %1; cvt.u32.u64 %0, t; }"
        : "=r"(a) : "l"(p));
    return a;
}

__device__ __forceinline__ void cp16(uint32_t dst, const void* src, int srcsize) {
    asm volatile("cp.async.cg.shared.global [%0], [%1], 16, %2;"
                 :: "r"(dst), "l"(src), "r"(srcsize));
}
#define CP_COMMIT() asm volatile("cp.async.commit_group;")
#define CP_WAIT0()  asm volatile("cp.async.wait_group 0;")

__device__ __forceinline__ void mma16816(float& c0, float& c1, float& c2, float& c3,
                                         const uint32_t a[4], const uint32_t* b) {
    asm volatile(
        "mma.sync.aligned.m16n8k16.row.col.f32.f16.f16.f32 "
        "{%0,%1,%2,%3},{%4,%5,%6,%7},{%8,%9},{%0,%1,%2,%3};"
        : "+f"(c0), "+f"(c1), "+f"(c2), "+f"(c3)
        : "r"(a[0]), "r"(a[1]), "r"(a[2]), "r"(a[3]), "r"(b[0]), "r"(b[1]));
}
#define MMA(C, A, B) mma16816((C)[0], (C)[1], (C)[2], (C)[3], A, B)

__device__ __forceinline__ void ldm_x4(uint32_t r[4], uint32_t addr) {
    asm volatile("ldmatrix.sync.aligned.m8n8.x4.shared.b16 {%0,%1,%2,%3}, [%4];"
                 : "=r"(r[0]), "=r"(r[1]), "=r"(r[2]), "=r"(r[3]) : "r"(addr));
}

// Row stride 80 B (conflict-free for cp.async stores and ldmatrix reads)
#define RSTR 80

// A fragment group (16 rows x 16 k): one ldmatrix.x4 -> mma operand order
__device__ __forceinline__ void fragA(uint32_t a[4], uint32_t tile, int rb, int k0, int lane) {
    uint32_t addr = tile + (uint32_t)(rb + (lane & 15)) * RSTR
                         + (uint32_t)(k0 + (lane >> 4) * 8) * 2;
    ldm_x4(a, addr);
}
// B fragment pair (two adjacent n-octets x 16 k from [n][k] tile)
__device__ __forceinline__ void fragB2(uint32_t b[4], uint32_t tile, int nb, int k0, int lane) {
    uint32_t addr = tile + (uint32_t)(nb + ((lane >> 4) * 8) + (lane & 7)) * RSTR
                         + (uint32_t)(k0 + ((lane >> 3) & 1) * 8) * 2;
    ldm_x4(b, addr);
}

// 128-row x 32-col fp16 tile via cp.async; per-thread sizes precomputed
__device__ __forceinline__ void load_tile128(uint32_t sdst, const __half* src,
                                             int ldk, int k0, int s0, int s1, int tid) {
    const int r = tid >> 2, c = tid & 3;
    cp16(sdst + r * RSTR + c * 16, src + (size_t)r * ldk + k0 + c * 8, s0);
    cp16(sdst + (r + 64) * RSTR + c * 16, src + (size_t)(r + 64) * ldk + k0 + c * 8, s1);
}
__device__ __forceinline__ void load_tile64(uint32_t sdst, const __half* src,
                                            int ldk, int k0, int tid) {
    const int r = tid >> 2, c = tid & 3;
    cp16(sdst + r * RSTR + c * 16, src + (size_t)r * ldk + k0 + c * 8, 16);
}

// ---------------------------------------------------------------------------
// Prep kernels
// ---------------------------------------------------------------------------
__global__ void convert_x(const float* __restrict__ x, const int* __restrict__ tpe) {
    if (blockIdx.x == 0 && threadIdx.x == 0) {
        int off = 0, nt = 0;
        for (int e = 0; e < NE; e++) {
            int n = tpe[e];
            for (int r = 0; r < n; r += 128) {
                g_tile_expert[nt] = e;
                g_tile_row0[nt]   = off + r;
                g_tile_nrows[nt]  = (n - r < 128) ? (n - r) : 128;
                nt++;
            }
            off += n;
        }
        g_ntiles = nt;
    }
    const size_t n4 = (size_t)TOT * HID / 4;
    for (size_t i = blockIdx.x * blockDim.x + threadIdx.x; i < n4;
         i += (size_t)gridDim.x * blockDim.x) {
        float4 v = ((const float4*)x)[i];
        __half2 p0 = __floats2half2_rn(v.x, v.y);
        __half2 p1 = __floats2half2_rn(v.z, v.w);
        ((uint2*)g_x)[i] = make_uint2(*(uint32_t*)&p0, *(uint32_t*)&p1);
    }
}

// z<NE: wg, z>=NE: wu.  [E][HID][INTER] fp32 -> [E][INTER][HID] fp16.
__global__ void transpose_cvt_gu(const float* __restrict__ wg,
                                 const float* __restrict__ wu) {
    __shared__ float t[32][33];
    const int z = blockIdx.z;
    const int e = z & (NE - 1);
    const bool isu = z >= NE;
    const float* src = (isu ? wu : wg) + (size_t)e * HID * INTER;
    __half* dst = (isu ? g_wu : g_wg) + (size_t)e * HID * INTER;
    const int k0 = blockIdx.x * 32, n0 = blockIdx.y * 32;
    const int tx = threadIdx.x, ty = threadIdx.y;
#pragma unroll
    for (int jj = 0; jj < 2; jj++) {
        const int kl = ty + jj * 16;
        float2 v = *(const float2*)(src + (size_t)(k0 + kl) * INTER + n0 + 2 * tx);
        t[kl][2 * tx] = v.x;
        t[kl][2 * tx + 1] = v.y;
    }
    __syncthreads();
#pragma unroll
    for (int jj = 0; jj < 2; jj++) {
        const int nl = ty + jj * 16;
        __half2 p = __floats2half2_rn(t[2 * tx][nl], t[2 * tx + 1][nl]);
        *(uint32_t*)(dst + (size_t)(n0 + nl) * HID + k0 + 2 * tx) = *(uint32_t*)&p;
    }
}

// [E][INTER][HID] fp32 -> [E][HID][INTER] fp16
__global__ void transpose_cvt_d(const float* __restrict__ wd) {
    __shared__ float t[32][33];
    const int e = blockIdx.z;
    const float* src = wd + (size_t)e * INTER * HID;
    __half* dst = g_wd + (size_t)e * INTER * HID;
    const int k0 = blockIdx.x * 32, n0 = blockIdx.y * 32;
    const int tx = threadIdx.x, ty = threadIdx.y;
#pragma unroll
    for (int jj = 0; jj < 2; jj++) {
        const int kl = ty + jj * 16;
        float2 v = *(const float2*)(src + (size_t)(k0 + kl) * HID + n0 + 2 * tx);
        t[kl][2 * tx] = v.x;
        t[kl][2 * tx + 1] = v.y;
    }
    __syncthreads();
#pragma unroll
    for (int jj = 0; jj < 2; jj++) {
        const int nl = ty + jj * 16;
        __half2 p = __floats2half2_rn(t[2 * tx][nl], t[2 * tx + 1][nl]);
        *(uint32_t*)(dst + (size_t)(n0 + nl) * INTER + k0 + 2 * tx) = *(uint32_t*)&p;
    }
}

// ---------------------------------------------------------------------------
// Fused gate+up grouped GEMM (fp16). CTA: M=128 x N=64 (per matrix), BK=32.
// 8 warps (4 M x 2 N), warp = 32x32 per matrix. 2-stage, 1 barrier/chunk.
// Stage (20480 B): A 0 (10240), G 10240 (5120), U 15360 (5120)
// ---------------------------------------------------------------------------
#define GU_BUF 20480
#define GU_SMEM (2 * GU_BUF)

__global__ void __launch_bounds__(256, 2) k_gateup() {
    const int t = blockIdx.y;
    if (t >= g_ntiles) return;
    const int e     = __ldg(&g_tile_expert[t]);
    const int row0  = __ldg(&g_tile_row0[t]);
    const int nrows = __ldg(&g_tile_nrows[t]);
    const int n0    = blockIdx.x * 64;

    extern __shared__ char smem[];
    const uint32_t sb = smem_u32(smem);
    const int tid  = threadIdx.x;
    const int lane = tid & 31;
    const int wid  = tid >> 5;
    const int wm   = wid & 3;
    const int wn   = wid >> 2;
    const int s0 = ((tid >> 2) < nrows) ? 16 : 0;
    const int s1 = ((tid >> 2) + 64 < nrows) ? 16 : 0;

    const __half* xp = g_x + (size_t)row0 * HID;
    const size_t wbase = (size_t)e * INTER * HID + (size_t)n0 * HID;
    const __half* gp = g_wg + wbase;
    const __half* up = g_wu + wbase;

    float cg[2][4][4], cu[2][4][4];
#pragma unroll
    for (int i = 0; i < 2; i++)
#pragma unroll
        for (int j = 0; j < 4; j++)
#pragma unroll
            for (int k = 0; k < 4; k++) { cg[i][j][k] = 0.f; cu[i][j][k] = 0.f; }

#define GU_LOAD(b, k0)                                              \
    do {                                                            \
        uint32_t o = sb + (b) * GU_BUF;                             \
        load_tile128(o,         xp, HID, (k0), s0, s1, tid);        \
        load_tile64(o + 10240,  gp, HID, (k0), tid);                \
        load_tile64(o + 15360,  up, HID, (k0), tid);                \
        CP_COMMIT();                                                \
    } while (0)

    GU_LOAD(0, 0);
    const int KT = HID / 32;
    for (int kt = 0; kt < KT; kt++) {
        CP_WAIT0();
        __syncthreads();
        if (kt + 1 < KT) GU_LOAD((kt + 1) & 1, (kt + 1) * 32);
        const uint32_t buf = sb + (kt & 1) * GU_BUF;
#pragma unroll
        for (int ks = 0; ks < 2; ks++) {
            const int k0 = ks * 16;
            uint32_t A0[4], A1[4];
            fragA(A0, buf, wm * 32,      k0, lane);
            fragA(A1, buf, wm * 32 + 16, k0, lane);
#pragma unroll
            for (int p = 0; p < 2; p++) {
                const int nb = wn * 32 + p * 16;
                uint32_t Bg[4], Bu[4];
                fragB2(Bg, buf + 10240, nb, k0, lane);
                fragB2(Bu, buf + 15360, nb, k0, lane);
                const int q = p * 2;
                MMA(cg[0][q],   A0, Bg);
                MMA(cg[1][q],   A1, Bg);
                MMA(cg[0][q+1], A0, Bg + 2);
                MMA(cg[1][q+1], A1, Bg + 2);
                MMA(cu[0][q],   A0, Bu);
                MMA(cu[1][q],   A1, Bu);
                MMA(cu[0][q+1], A0, Bu + 2);
                MMA(cu[1][q+1], A1, Bu + 2);
            }
        }
    }

    // epilogue: silu(gate)*up -> h (fp16)
#pragma unroll
    for (int mt = 0; mt < 2; mt++)
#pragma unroll
        for (int half = 0; half < 2; half++) {
            const int r = wm * 32 + mt * 16 + half * 8 + (lane >> 2);
            if (r < nrows) {
                __half* hp = g_h + (size_t)(row0 + r) * INTER + n0 + wn * 32;
#pragma unroll
                for (int nt = 0; nt < 4; nt++) {
                    const float gg0 = cg[mt][nt][half * 2], gg1 = cg[mt][nt][half * 2 + 1];
                    const float uu0 = cu[mt][nt][half * 2], uu1 = cu[mt][nt][half * 2 + 1];
                    const float h0 = uu0 * gg0 / (1.f + __expf(-gg0));
                    const float h1 = uu1 * gg1 / (1.f + __expf(-gg1));
                    __half2 p = __floats2half2_rn(h0, h1);
                    *(uint32_t*)(hp + nt * 8 + (lane & 3) * 2) = *(uint32_t*)&p;
                }
            }
        }
}

// ---------------------------------------------------------------------------
// Down grouped GEMM (fp16). CTA: M=128 x N=128, BK=32, 8 warps (4 x 2), warp 32x64.
// Stage (20480 B): A 0 (10240), B 10240 (10240)
// ---------------------------------------------------------------------------
#define DN_BUF 20480
#define DN_SMEM (2 * DN_BUF)

__global__ void __launch_bounds__(256, 2) k_down(const float* __restrict__ probs,
                                                 float* __restrict__ out) {
    const int t = blockIdx.y;
    if (t >= g_ntiles) return;
    const int e     = __ldg(&g_tile_expert[t]);
    const int row0  = __ldg(&g_tile_row0[t]);
    const int nrows = __ldg(&g_tile_nrows[t]);
    const int n0    = blockIdx.x * 128;

    extern __shared__ char smem[];
    const uint32_t sb = smem_u32(smem);
    const int tid  = threadIdx.x;
    const int lane = tid & 31;
    const int wid  = tid >> 5;
    const int wm   = wid & 3;
    const int wn   = wid >> 2;
    const int s0 = ((tid >> 2) < nrows) ? 16 : 0;
    const int s1 = ((tid >> 2) + 64 < nrows) ? 16 : 0;

    const __half* ap = g_h + (size_t)row0 * INTER;
    const size_t wbase = (size_t)e * HID * INTER + (size_t)n0 * INTER;
    const __half* bp = g_wd + wbase;

    float cc[2][8][4];
#pragma unroll
    for (int i = 0; i < 2; i++)
#pragma unroll
        for (int j = 0; j < 8; j++)
#pragma unroll
            for (int k = 0; k < 4; k++) cc[i][j][k] = 0.f;

#define DN_LOAD(b, k0)                                                  \
    do {                                                                \
        uint32_t o = sb + (b) * DN_BUF;                                 \
        load_tile128(o,         ap, INTER, (k0), s0, s1, tid);          \
        load_tile128(o + 10240, bp, INTER, (k0), 16, 16, tid);          \
        CP_COMMIT();                                                    \
    } while (0)

    DN_LOAD(0, 0);
    const int KT = INTER / 32;
    for (int kt = 0; kt < KT; kt++) {
        CP_WAIT0();
        __syncthreads();
        if (kt + 1 < KT) DN_LOAD((kt + 1) & 1, (kt + 1) * 32);
        const uint32_t buf = sb + (kt & 1) * DN_BUF;
#pragma unroll
        for (int ks = 0; ks < 2; ks++) {
            const int k0 = ks * 16;
            uint32_t A0[4], A1[4];
            fragA(A0, buf, wm * 32,      k0, lane);
            fragA(A1, buf, wm * 32 + 16, k0, lane);
#pragma unroll
            for (int p = 0; p < 4; p++) {
                const int nb = wn * 64 + p * 16;
                uint32_t Fb[4];
                fragB2(Fb, buf + 10240, nb, k0, lane);
                const int q = p * 2;
                MMA(cc[0][q],   A0, Fb);
                MMA(cc[1][q],   A1, Fb);
                MMA(cc[0][q+1], A0, Fb + 2);
                MMA(cc[1][q+1], A1, Fb + 2);
            }
        }
    }

    // epilogue: scale by probs, write fp32 out
#pragma unroll
    for (int mt = 0; mt < 2; mt++)
#pragma unroll
        for (int half = 0; half < 2; half++) {
            const int r = wm * 32 + mt * 16 + half * 8 + (lane >> 2);
            if (r < nrows) {
                const float p = probs[row0 + r];
                float* op = out + (size_t)(row0 + r) * HID + n0 + wn * 64;
#pragma unroll
                for (int nt = 0; nt < 8; nt++) {
                    const int col = nt * 8 + (lane & 3) * 2;
                    float2 v;
                    v.x = p * cc[mt][nt][half * 2];
                    v.y = p * cc[mt][nt][half * 2 + 1];
                    *(float2*)(op + col) = v;
                }
            }
        }
}

// ---------------------------------------------------------------------------
// Launch
// ---------------------------------------------------------------------------
extern "C" void kernel_launch(void* const* d_in, const int* in_sizes, int n_in,
                              void* d_out, int out_size) {
    const float* x     = (const float*)d_in[0];
    const float* probs = (const float*)d_in[1];
    const float* wg    = (const float*)d_in[2];
    const float* wu    = (const float*)d_in[3];
    const float* wd    = (const float*)d_in[4];
    const int*   tpe   = (const int*)d_in[5];
    float*       out   = (float*)d_out;

    cudaFuncSetAttribute(k_gateup, cudaFuncAttributeMaxDynamicSharedMemorySize, GU_SMEM);
    cudaFuncSetAttribute(k_down,   cudaFuncAttributeMaxDynamicSharedMemorySize, DN_SMEM);

    convert_x<<<2048, 256>>>(x, tpe);

    dim3 tb(16, 16);
    transpose_cvt_gu<<<dim3(HID / 32, INTER / 32, 2 * NE), tb>>>(wg, wu);
    transpose_cvt_d<<<dim3(INTER / 32, HID / 32, NE), tb>>>(wd);

    k_gateup<<<dim3(INTER / 64, MAXGRIDY), 256, GU_SMEM>>>();
    k_down<<<dim3(HID / 128, MAXGRIDY), 256, DN_SMEM>>>(probs, out);
}

// round 11
// speedup vs baseline: 2.3281x; 1.0007x over previous
#include <cuda_runtime.h>
#include <cuda_fp16.h>
#include <stdint.h>
#include <math.h>

#define NE 8
#define HID 2048
#define INTER 1408
#define TOT 8192
#define MAXTILES 96
#define MAXGRIDY 72

// ---------------------------------------------------------------------------
// Device globals (fp16 single plane everywhere)
// ---------------------------------------------------------------------------
__device__ int g_tile_expert[MAXTILES];
__device__ int g_tile_row0[MAXTILES];
__device__ int g_tile_nrows[MAXTILES];
__device__ int g_ntiles;

__device__ __half g_x[(size_t)TOT * HID];
// transposed weights: [E][N][K], K contiguous
__device__ __half g_wg[(size_t)NE * INTER * HID];
__device__ __half g_wu[(size_t)NE * INTER * HID];
__device__ __half g_wd[(size_t)NE * HID * INTER];
__device__ __half g_h[(size_t)TOT * INTER];

// ---------------------------------------------------------------------------
// Helpers (base-target PTX: mma.sync sm_80, cp.async sm_80, ldmatrix sm_75)
// ---------------------------------------------------------------------------
__device__ __forceinline__ uint32_t smem_u32(const void* p) {
    uint32_t a;
    asm("{ .reg .u64 t; cvta.to.shared.u64 t, %1; cvt.u32.u64 %0, t; }"
        : "=r"(a) : "l"(p));
    return a;
}

__device__ __forceinline__ void cp16(uint32_t dst, const void* src, int srcsize) {
    asm volatile("cp.async.cg.shared.global [%0], [%1], 16, %2;"
                 :: "r"(dst), "l"(src), "r"(srcsize));
}
#define CP_COMMIT() asm volatile("cp.async.commit_group;")
#define CP_WAIT0()  asm volatile("cp.async.wait_group 0;")

__device__ __forceinline__ void mma16816(float& c0, float& c1, float& c2, float& c3,
                                         const uint32_t a[4], const uint32_t* b) {
    asm volatile(
        "mma.sync.aligned.m16n8k16.row.col.f32.f16.f16.f32 "
        "{%0,%1,%2,%3},{%4,%5,%6,%7},{%8,%9},{%0,%1,%2,%3};"
        : "+f"(c0), "+f"(c1), "+f"(c2), "+f"(c3)
        : "r"(a[0]), "r"(a[1]), "r"(a[2]), "r"(a[3]), "r"(b[0]), "r"(b[1]));
}
#define MMA(C, A, B) mma16816((C)[0], (C)[1], (C)[2], (C)[3], A, B)

__device__ __forceinline__ void ldm_x4(uint32_t r[4], uint32_t addr) {
    asm volatile("ldmatrix.sync.aligned.m8n8.x4.shared.b16 {%0,%1,%2,%3}, [%4];"
                 : "=r"(r[0]), "=r"(r[1]), "=r"(r[2]), "=r"(r[3]) : "r"(addr));
}

// Row stride 80 B (conflict-free for cp.async stores and ldmatrix reads)
#define RSTR 80

// A fragment group (16 rows x 16 k): one ldmatrix.x4 -> mma operand order
__device__ __forceinline__ void fragA(uint32_t a[4], uint32_t tile, int rb, int k0, int lane) {
    uint32_t addr = tile + (uint32_t)(rb + (lane & 15)) * RSTR
                         + (uint32_t)(k0 + (lane >> 4) * 8) * 2;
    ldm_x4(a, addr);
}
// B fragment pair (two adjacent n-octets x 16 k from [n][k] tile)
__device__ __forceinline__ void fragB2(uint32_t b[4], uint32_t tile, int nb, int k0, int lane) {
    uint32_t addr = tile + (uint32_t)(nb + ((lane >> 4) * 8) + (lane & 7)) * RSTR
                         + (uint32_t)(k0 + ((lane >> 3) & 1) * 8) * 2;
    ldm_x4(b, addr);
}

// 128-row x 32-col fp16 tile via cp.async; per-thread sizes precomputed
__device__ __forceinline__ void load_tile128(uint32_t sdst, const __half* src,
                                             int ldk, int k0, int s0, int s1, int tid) {
    const int r = tid >> 2, c = tid & 3;
    cp16(sdst + r * RSTR + c * 16, src + (size_t)r * ldk + k0 + c * 8, s0);
    cp16(sdst + (r + 64) * RSTR + c * 16, src + (size_t)(r + 64) * ldk + k0 + c * 8, s1);
}
__device__ __forceinline__ void load_tile64(uint32_t sdst, const __half* src,
                                            int ldk, int k0, int tid) {
    const int r = tid >> 2, c = tid & 3;
    cp16(sdst + r * RSTR + c * 16, src + (size_t)r * ldk + k0 + c * 8, 16);
}

// ---------------------------------------------------------------------------
// Prep kernels
// ---------------------------------------------------------------------------
__global__ void convert_x(const float* __restrict__ x, const int* __restrict__ tpe) {
    if (blockIdx.x == 0 && threadIdx.x == 0) {
        int off = 0, nt = 0;
        for (int e = 0; e < NE; e++) {
            int n = tpe[e];
            for (int r = 0; r < n; r += 128) {
                g_tile_expert[nt] = e;
                g_tile_row0[nt]   = off + r;
                g_tile_nrows[nt]  = (n - r < 128) ? (n - r) : 128;
                nt++;
            }
            off += n;
        }
        g_ntiles = nt;
    }
    const size_t n4 = (size_t)TOT * HID / 4;
    for (size_t i = blockIdx.x * blockDim.x + threadIdx.x; i < n4;
         i += (size_t)gridDim.x * blockDim.x) {
        float4 v = ((const float4*)x)[i];
        __half2 p0 = __floats2half2_rn(v.x, v.y);
        __half2 p1 = __floats2half2_rn(v.z, v.w);
        ((uint2*)g_x)[i] = make_uint2(*(uint32_t*)&p0, *(uint32_t*)&p1);
    }
}

// z<NE: wg, z>=NE: wu.  [E][HID][INTER] fp32 -> [E][INTER][HID] fp16.
__global__ void transpose_cvt_gu(const float* __restrict__ wg,
                                 const float* __restrict__ wu) {
    __shared__ float t[32][33];
    const int z = blockIdx.z;
    const int e = z & (NE - 1);
    const bool isu = z >= NE;
    const float* src = (isu ? wu : wg) + (size_t)e * HID * INTER;
    __half* dst = (isu ? g_wu : g_wg) + (size_t)e * HID * INTER;
    const int k0 = blockIdx.x * 32, n0 = blockIdx.y * 32;
    const int tx = threadIdx.x, ty = threadIdx.y;
#pragma unroll
    for (int jj = 0; jj < 2; jj++) {
        const int kl = ty + jj * 16;
        float2 v = *(const float2*)(src + (size_t)(k0 + kl) * INTER + n0 + 2 * tx);
        t[kl][2 * tx] = v.x;
        t[kl][2 * tx + 1] = v.y;
    }
    __syncthreads();
#pragma unroll
    for (int jj = 0; jj < 2; jj++) {
        const int nl = ty + jj * 16;
        __half2 p = __floats2half2_rn(t[2 * tx][nl], t[2 * tx + 1][nl]);
        *(uint32_t*)(dst + (size_t)(n0 + nl) * HID + k0 + 2 * tx) = *(uint32_t*)&p;
    }
}

// [E][INTER][HID] fp32 -> [E][HID][INTER] fp16
__global__ void transpose_cvt_d(const float* __restrict__ wd) {
    __shared__ float t[32][33];
    const int e = blockIdx.z;
    const float* src = wd + (size_t)e * INTER * HID;
    __half* dst = g_wd + (size_t)e * INTER * HID;
    const int k0 = blockIdx.x * 32, n0 = blockIdx.y * 32;
    const int tx = threadIdx.x, ty = threadIdx.y;
#pragma unroll
    for (int jj = 0; jj < 2; jj++) {
        const int kl = ty + jj * 16;
        float2 v = *(const float2*)(src + (size_t)(k0 + kl) * HID + n0 + 2 * tx);
        t[kl][2 * tx] = v.x;
        t[kl][2 * tx + 1] = v.y;
    }
    __syncthreads();
#pragma unroll
    for (int jj = 0; jj < 2; jj++) {
        const int nl = ty + jj * 16;
        __half2 p = __floats2half2_rn(t[2 * tx][nl], t[2 * tx + 1][nl]);
        *(uint32_t*)(dst + (size_t)(n0 + nl) * INTER + k0 + 2 * tx) = *(uint32_t*)&p;
    }
}

// ---------------------------------------------------------------------------
// Fused gate+up grouped GEMM (fp16). CTA: M=128 x N=64 (per matrix), BK=64
// (two 32-k sub-tiles per stage). 8 warps (4M x 2N), warp 32x32 per matrix.
// 2-stage, 1 barrier per 64-k chunk.
// Stage (40960 B): A sub0 0, A sub1 10240, G sub0 20480, G sub1 25600,
//                  U sub0 30720, U sub1 35840
// ---------------------------------------------------------------------------
#define GU_BUF 40960
#define GU_SMEM (2 * GU_BUF)

__global__ void __launch_bounds__(256, 2) k_gateup() {
    const int t = blockIdx.y;
    if (t >= g_ntiles) return;
    const int e     = __ldg(&g_tile_expert[t]);
    const int row0  = __ldg(&g_tile_row0[t]);
    const int nrows = __ldg(&g_tile_nrows[t]);
    const int n0    = blockIdx.x * 64;

    extern __shared__ char smem[];
    const uint32_t sb = smem_u32(smem);
    const int tid  = threadIdx.x;
    const int lane = tid & 31;
    const int wid  = tid >> 5;
    const int wm   = wid & 3;
    const int wn   = wid >> 2;
    const int s0 = ((tid >> 2) < nrows) ? 16 : 0;
    const int s1 = ((tid >> 2) + 64 < nrows) ? 16 : 0;

    const __half* xp = g_x + (size_t)row0 * HID;
    const size_t wbase = (size_t)e * INTER * HID + (size_t)n0 * HID;
    const __half* gp = g_wg + wbase;
    const __half* up = g_wu + wbase;

    float cg[2][4][4], cu[2][4][4];
#pragma unroll
    for (int i = 0; i < 2; i++)
#pragma unroll
        for (int j = 0; j < 4; j++)
#pragma unroll
            for (int k = 0; k < 4; k++) { cg[i][j][k] = 0.f; cu[i][j][k] = 0.f; }

// load one 64-k chunk = two 32-k sub-tiles per operand
#define GU_LOAD(b, k0)                                                  \
    do {                                                                \
        uint32_t o = sb + (b) * GU_BUF;                                 \
        load_tile128(o,         xp, HID, (k0),      s0, s1, tid);       \
        load_tile128(o + 10240, xp, HID, (k0) + 32, s0, s1, tid);       \
        load_tile64(o + 20480,  gp, HID, (k0),      tid);               \
        load_tile64(o + 25600,  gp, HID, (k0) + 32, tid);               \
        load_tile64(o + 30720,  up, HID, (k0),      tid);               \
        load_tile64(o + 35840,  up, HID, (k0) + 32, tid);               \
        CP_COMMIT();                                                    \
    } while (0)

    GU_LOAD(0, 0);
    const int KC = HID / 64;   // 32 chunks
    for (int kc = 0; kc < KC; kc++) {
        CP_WAIT0();
        __syncthreads();
        if (kc + 1 < KC) GU_LOAD((kc + 1) & 1, (kc + 1) * 64);
        const uint32_t buf = sb + (kc & 1) * GU_BUF;
#pragma unroll
        for (int ks = 0; ks < 4; ks++) {
            const int sub = ks >> 1;
            const int k0  = (ks & 1) * 16;
            const uint32_t bufA = buf + sub * 10240;
            const uint32_t bufG = buf + 20480 + sub * 5120;
            const uint32_t bufU = buf + 30720 + sub * 5120;
            uint32_t A0[4], A1[4];
            fragA(A0, bufA, wm * 32,      k0, lane);
            fragA(A1, bufA, wm * 32 + 16, k0, lane);
#pragma unroll
            for (int p = 0; p < 2; p++) {
                const int nb = wn * 32 + p * 16;
                uint32_t Bg[4], Bu[4];
                fragB2(Bg, bufG, nb, k0, lane);
                fragB2(Bu, bufU, nb, k0, lane);
                const int q = p * 2;
                MMA(cg[0][q],   A0, Bg);
                MMA(cg[1][q],   A1, Bg);
                MMA(cg[0][q+1], A0, Bg + 2);
                MMA(cg[1][q+1], A1, Bg + 2);
                MMA(cu[0][q],   A0, Bu);
                MMA(cu[1][q],   A1, Bu);
                MMA(cu[0][q+1], A0, Bu + 2);
                MMA(cu[1][q+1], A1, Bu + 2);
            }
        }
    }

    // epilogue: silu(gate)*up -> h (fp16)
#pragma unroll
    for (int mt = 0; mt < 2; mt++)
#pragma unroll
        for (int half = 0; half < 2; half++) {
            const int r = wm * 32 + mt * 16 + half * 8 + (lane >> 2);
            if (r < nrows) {
                __half* hp = g_h + (size_t)(row0 + r) * INTER + n0 + wn * 32;
#pragma unroll
                for (int nt = 0; nt < 4; nt++) {
                    const float gg0 = cg[mt][nt][half * 2], gg1 = cg[mt][nt][half * 2 + 1];
                    const float uu0 = cu[mt][nt][half * 2], uu1 = cu[mt][nt][half * 2 + 1];
                    const float h0 = uu0 * gg0 / (1.f + __expf(-gg0));
                    const float h1 = uu1 * gg1 / (1.f + __expf(-gg1));
                    __half2 p = __floats2half2_rn(h0, h1);
                    *(uint32_t*)(hp + nt * 8 + (lane & 3) * 2) = *(uint32_t*)&p;
                }
            }
        }
}

// ---------------------------------------------------------------------------
// Down grouped GEMM (fp16). CTA: M=128 x N=128, BK=64 (two 32-k sub-tiles).
// 8 warps (4 x 2), warp 32x64. 2-stage, 1 barrier per 64-k chunk.
// Stage (40960 B): A sub0 0, A sub1 10240, B sub0 20480, B sub1 30720
// ---------------------------------------------------------------------------
#define DN_BUF 40960
#define DN_SMEM (2 * DN_BUF)

__global__ void __launch_bounds__(256, 2) k_down(const float* __restrict__ probs,
                                                 float* __restrict__ out) {
    const int t = blockIdx.y;
    if (t >= g_ntiles) return;
    const int e     = __ldg(&g_tile_expert[t]);
    const int row0  = __ldg(&g_tile_row0[t]);
    const int nrows = __ldg(&g_tile_nrows[t]);
    const int n0    = blockIdx.x * 128;

    extern __shared__ char smem[];
    const uint32_t sb = smem_u32(smem);
    const int tid  = threadIdx.x;
    const int lane = tid & 31;
    const int wid  = tid >> 5;
    const int wm   = wid & 3;
    const int wn   = wid >> 2;
    const int s0 = ((tid >> 2) < nrows) ? 16 : 0;
    const int s1 = ((tid >> 2) + 64 < nrows) ? 16 : 0;

    const __half* ap = g_h + (size_t)row0 * INTER;
    const size_t wbase = (size_t)e * HID * INTER + (size_t)n0 * INTER;
    const __half* bp = g_wd + wbase;

    float cc[2][8][4];
#pragma unroll
    for (int i = 0; i < 2; i++)
#pragma unroll
        for (int j = 0; j < 8; j++)
#pragma unroll
            for (int k = 0; k < 4; k++) cc[i][j][k] = 0.f;

#define DN_LOAD(b, k0)                                                  \
    do {                                                                \
        uint32_t o = sb + (b) * DN_BUF;                                 \
        load_tile128(o,         ap, INTER, (k0),      s0, s1, tid);     \
        load_tile128(o + 10240, ap, INTER, (k0) + 32, s0, s1, tid);     \
        load_tile128(o + 20480, bp, INTER, (k0),      16, 16, tid);     \
        load_tile128(o + 30720, bp, INTER, (k0) + 32, 16, 16, tid);     \
        CP_COMMIT();                                                    \
    } while (0)

    DN_LOAD(0, 0);
    const int KC = INTER / 64;  // 22 chunks
    for (int kc = 0; kc < KC; kc++) {
        CP_WAIT0();
        __syncthreads();
        if (kc + 1 < KC) DN_LOAD((kc + 1) & 1, (kc + 1) * 64);
        const uint32_t buf = sb + (kc & 1) * DN_BUF;
#pragma unroll
        for (int ks = 0; ks < 4; ks++) {
            const int sub = ks >> 1;
            const int k0  = (ks & 1) * 16;
            const uint32_t bufA = buf + sub * 10240;
            const uint32_t bufB = buf + 20480 + sub * 10240;
            uint32_t A0[4], A1[4];
            fragA(A0, bufA, wm * 32,      k0, lane);
            fragA(A1, bufA, wm * 32 + 16, k0, lane);
#pragma unroll
            for (int p = 0; p < 4; p++) {
                const int nb = wn * 64 + p * 16;
                uint32_t Fb[4];
                fragB2(Fb, bufB, nb, k0, lane);
                const int q = p * 2;
                MMA(cc[0][q],   A0, Fb);
                MMA(cc[1][q],   A1, Fb);
                MMA(cc[0][q+1], A0, Fb + 2);
                MMA(cc[1][q+1], A1, Fb + 2);
            }
        }
    }

    // epilogue: scale by probs, write fp32 out
#pragma unroll
    for (int mt = 0; mt < 2; mt++)
#pragma unroll
        for (int half = 0; half < 2; half++) {
            const int r = wm * 32 + mt * 16 + half * 8 + (lane >> 2);
            if (r < nrows) {
                const float p = probs[row0 + r];
                float* op = out + (size_t)(row0 + r) * HID + n0 + wn * 64;
#pragma unroll
                for (int nt = 0; nt < 8; nt++) {
                    const int col = nt * 8 + (lane & 3) * 2;
                    float2 v;
                    v.x = p * cc[mt][nt][half * 2];
                    v.y = p * cc[mt][nt][half * 2 + 1];
                    *(float2*)(op + col) = v;
                }
            }
        }
}

// ---------------------------------------------------------------------------
// Launch
// ---------------------------------------------------------------------------
extern "C" void kernel_launch(void* const* d_in, const int* in_sizes, int n_in,
                              void* d_out, int out_size) {
    const float* x     = (const float*)d_in[0];
    const float* probs = (const float*)d_in[1];
    const float* wg    = (const float*)d_in[2];
    const float* wu    = (const float*)d_in[3];
    const float* wd    = (const float*)d_in[4];
    const int*   tpe   = (const int*)d_in[5];
    float*       out   = (float*)d_out;

    cudaFuncSetAttribute(k_gateup, cudaFuncAttributeMaxDynamicSharedMemorySize, GU_SMEM);
    cudaFuncSetAttribute(k_down,   cudaFuncAttributeMaxDynamicSharedMemorySize, DN_SMEM);

    convert_x<<<2048, 256>>>(x, tpe);

    dim3 tb(16, 16);
    transpose_cvt_gu<<<dim3(HID / 32, INTER / 32, 2 * NE), tb>>>(wg, wu);
    transpose_cvt_d<<<dim3(INTER / 32, HID / 32, NE), tb>>>(wd);

    k_gateup<<<dim3(INTER / 64, MAXGRIDY), 256, GU_SMEM>>>();
    k_down<<<dim3(HID / 128, MAXGRIDY), 256, DN_SMEM>>>(probs, out);
}